// round 11
// baseline (speedup 1.0000x reference)
#include <cuda_runtime.h>
#include <cuda_fp16.h>
#include <cstdint>

#define NN 10000
#define EE 640000
#define D  128
#define M2 (2*NN)
#define GEMM_BLOCKS ((M2 + 127) / 128)      // 157

// ---------------- scratch (static __device__, no allocation) ----------------
__device__ int   g_is64;
__device__ int   g_deg[NN];
__device__ int   g_rowptr[NN + 1];
__device__ float g_dinv[NN];
__device__ int   g_rank[EE];
__device__ int   g_src[EE];
__device__ __align__(16) float  g_H[(size_t)M2 * D];     // node features (both seqs)
__device__ __align__(16) __half g_Yh[(size_t)NN * 256];  // interleaved node row: 256 halves (seq1|seq2)
__device__ float g_colsum[D];
__device__ float g_wc[D];

__device__ __forceinline__ unsigned h2_bits(__half2 h) {
    union { __half2 h; unsigned u; } cv; cv.h = h; return cv.u;
}
__device__ __forceinline__ uint32_t smem_u32(const void* p) {
    uint32_t a;
    asm("{ .reg .u64 t; cvta.to.shared.u64 t, %1; cvt.u32.u64 %0, t; }"
        : "=r"(a) : "l"(p));
    return a;
}

// ---------------- init + dtype probe (int64 => odd int32 words all zero) ----
__global__ void init_kernel(const int* __restrict__ ei32) {
    if (blockIdx.x == 0 && threadIdx.x < 32) {
        int odd = ei32[2 * threadIdx.x + 1];
        unsigned m = __ballot_sync(0xffffffffu, odd != 0);
        if (threadIdx.x == 0) g_is64 = (m == 0);
    }
    int i = blockIdx.x * blockDim.x + threadIdx.x;
    if (i < NN) g_deg[i] = 0;
    if (i < D)  g_colsum[i] = 0.f;
}

// -------- edge loaders: 8 edges/thread --------
__device__ __forceinline__ void load_cols8(const void* ei, int e, int* c) {
    if (g_is64) {
        const ulonglong2* p = (const ulonglong2*)((const long long*)ei + EE + e);
        ulonglong2 v0 = p[0], v1 = p[1], v2 = p[2], v3 = p[3];
        c[0] = (int)v0.x; c[1] = (int)v0.y; c[2] = (int)v1.x; c[3] = (int)v1.y;
        c[4] = (int)v2.x; c[5] = (int)v2.y; c[6] = (int)v3.x; c[7] = (int)v3.y;
    } else {
        int4 v0 = *(const int4*)((const int*)ei + EE + e);
        int4 v1 = *(const int4*)((const int*)ei + EE + e + 4);
        c[0] = v0.x; c[1] = v0.y; c[2] = v0.z; c[3] = v0.w;
        c[4] = v1.x; c[5] = v1.y; c[6] = v1.z; c[7] = v1.w;
    }
}
__device__ __forceinline__ void load_rows8(const void* ei, int e, int* r) {
    if (g_is64) {
        const ulonglong2* p = (const ulonglong2*)((const long long*)ei + e);
        ulonglong2 v0 = p[0], v1 = p[1], v2 = p[2], v3 = p[3];
        r[0] = (int)v0.x; r[1] = (int)v0.y; r[2] = (int)v1.x; r[3] = (int)v1.y;
        r[4] = (int)v2.x; r[5] = (int)v2.y; r[6] = (int)v3.x; r[7] = (int)v3.y;
    } else {
        int4 v0 = *(const int4*)((const int*)ei + e);
        int4 v1 = *(const int4*)((const int*)ei + e + 4);
        r[0] = v0.x; r[1] = v0.y; r[2] = v0.z; r[3] = v0.w;
        r[4] = v1.x; r[5] = v1.y; r[6] = v1.z; r[7] = v1.w;
    }
}

// ---------------- histogram + per-edge rank: 8 edges/thread ----------------
__global__ void hist_kernel(const void* __restrict__ ei) {
    int e = (blockIdx.x * blockDim.x + threadIdx.x) * 8;
    if (e >= EE) return;
    int c[8], rk[8];
    load_cols8(ei, e, c);
#pragma unroll
    for (int j = 0; j < 8; j++)
        rk[j] = ((unsigned)c[j] < NN) ? atomicAdd(&g_deg[c[j]], 1) : -1;
    *(int4*)(g_rank + e)     = make_int4(rk[0], rk[1], rk[2], rk[3]);
    *(int4*)(g_rank + e + 4) = make_int4(rk[4], rk[5], rk[6], rk[7]);
}

// single block, 1024 threads, 10 elems/thread
__global__ void scan_kernel() {
    const int PER = 10;
    int tid  = threadIdx.x;
    int lane = tid & 31, w = tid >> 5;
    int base = tid * PER;
    int v[PER];
    int s = 0;
#pragma unroll
    for (int k = 0; k < PER; k++) {
        int i = base + k;
        int d = (i < NN) ? g_deg[i] : 0;
        v[k] = d; s += d;
        if (i < NN) g_dinv[i] = rsqrtf((float)(d + 1));
    }
    int ws = s;
#pragma unroll
    for (int o = 1; o < 32; o <<= 1) {
        int t = __shfl_up_sync(0xffffffffu, ws, o);
        if (lane >= o) ws += t;
    }
    __shared__ int wsum[32];
    if (lane == 31) wsum[w] = ws;
    __syncthreads();
    if (w == 0) {
        int x = wsum[lane];
#pragma unroll
        for (int o = 1; o < 32; o <<= 1) {
            int t = __shfl_up_sync(0xffffffffu, x, o);
            if (lane >= o) x += t;
        }
        wsum[lane] = x;
    }
    __syncthreads();
    int run = ws - s + (w ? wsum[w - 1] : 0);
#pragma unroll
    for (int k = 0; k < PER; k++) {
        int i = base + k;
        if (i <= NN) g_rowptr[i] = run;
        run += v[k];
    }
}

// ---------------- CSR fill: atomic-free, 8 edges/thread ----------------
__global__ void fill_kernel(const void* __restrict__ ei) {
    int e = (blockIdx.x * blockDim.x + threadIdx.x) * 8;
    if (e >= EE) return;
    int r[8], c[8];
    load_rows8(ei, e, r);
    load_cols8(ei, e, c);
    int4 k0 = *(const int4*)(g_rank + e);
    int4 k1 = *(const int4*)(g_rank + e + 4);
    int rk[8] = {k0.x, k0.y, k0.z, k0.w, k1.x, k1.y, k1.z, k1.w};
#pragma unroll
    for (int j = 0; j < 8; j++)
        if (rk[j] >= 0 && (unsigned)r[j] < NN)
            g_src[g_rowptr[c[j]] + rk[j]] = r[j];
}

// ---------------- split-fp16 HMMA GEMM: Yh = half( dinv .* (A @ W) ) --------
#define WSTR 136

__global__ __launch_bounds__(256) void gemm_mma_kernel(const float* __restrict__ W,
                                                       const float* __restrict__ A0,
                                                       const float* __restrict__ A1) {
    __shared__ __half Wh[64 * WSTR];
    __shared__ __half Wl[64 * WSTR];
    int tid = threadIdx.x, wid = tid >> 5, lane = tid & 31;
    int bm = blockIdx.x * 128;
    const float* base0 = A0 ? A0 : g_H;
    const float* base1 = A0 ? A1 : (g_H + (size_t)NN * D);

    int grpID = lane >> 2, tig = lane & 3;
    int m0 = bm + wid * 16 + grpID;
    int m1 = m0 + 8;
    int m0c = (m0 < M2) ? m0 : M2 - 1;
    int m1c = (m1 < M2) ? m1 : M2 - 1;
    const float* ap0 = (m0c < NN) ? (base0 + (size_t)m0c * D)
                                  : (base1 + (size_t)(m0c - NN) * D);
    const float* ap1 = (m1c < NN) ? (base0 + (size_t)m1c * D)
                                  : (base1 + (size_t)(m1c - NN) * D);

    float c[16][4];
#pragma unroll
    for (int t = 0; t < 16; t++)
#pragma unroll
        for (int j = 0; j < 4; j++) c[t][j] = 0.f;

    int krow = lane & 15;
    int ngrp = (lane >> 4) * 8;

    for (int phase = 0; phase < 2; phase++) {
        for (int idx = tid; idx < 64 * 32; idx += 256) {
            int row = idx >> 5, c4 = (idx & 31) * 4;
            float4 v = *(const float4*)(W + (size_t)(phase * 64 + row) * D + c4);
            __half hx = __float2half_rn(v.x), hy = __float2half_rn(v.y);
            __half hz = __float2half_rn(v.z), hw = __float2half_rn(v.w);
            uint2 hi, lo;
            hi.x = h2_bits(__halves2half2(hx, hy));
            hi.y = h2_bits(__halves2half2(hz, hw));
            lo.x = h2_bits(__floats2half2_rn(v.x - __half2float(hx),
                                             v.y - __half2float(hy)));
            lo.y = h2_bits(__floats2half2_rn(v.z - __half2float(hz),
                                             v.w - __half2float(hw)));
            *(uint2*)(Wh + row * WSTR + c4) = hi;
            *(uint2*)(Wl + row * WSTR + c4) = lo;
        }
        __syncthreads();

#pragma unroll
        for (int kt = 0; kt < 4; kt++) {
            int kc = phase * 64 + kt * 16 + tig * 2;
            uint32_t ah[4], al[4];
#pragma unroll
            for (int q = 0; q < 4; q++) {
                const float* ap = (q & 1) ? ap1 : ap0;
                float2 v = *(const float2*)(ap + kc + (q >> 1) * 8);
                __half hx = __float2half_rn(v.x), hy = __float2half_rn(v.y);
                ah[q] = h2_bits(__halves2half2(hx, hy));
                al[q] = h2_bits(__floats2half2_rn(v.x - __half2float(hx),
                                                  v.y - __half2float(hy)));
            }

            uint32_t rowoff = (uint32_t)(kt * 16 + krow) * WSTR * 2 + ngrp * 2;
            uint32_t bh_addr = smem_u32(Wh) + rowoff;
            uint32_t bl_addr = smem_u32(Wl) + rowoff;
#pragma unroll
            for (int nt = 0; nt < 8; nt++) {
                uint32_t bh0, bh1, bh2, bh3, bl0, bl1, bl2, bl3;
                asm volatile(
                    "ldmatrix.sync.aligned.m8n8.x4.trans.shared.b16 {%0,%1,%2,%3}, [%4];"
                    : "=r"(bh0), "=r"(bh1), "=r"(bh2), "=r"(bh3)
                    : "r"(bh_addr + nt * 32));
                asm volatile(
                    "ldmatrix.sync.aligned.m8n8.x4.trans.shared.b16 {%0,%1,%2,%3}, [%4];"
                    : "=r"(bl0), "=r"(bl1), "=r"(bl2), "=r"(bl3)
                    : "r"(bl_addr + nt * 32));
#define MMA(CT, B0, B1, AH0, AH1, AH2, AH3)                                   \
    asm volatile(                                                             \
        "mma.sync.aligned.m16n8k16.row.col.f32.f16.f16.f32 "                  \
        "{%0,%1,%2,%3}, {%4,%5,%6,%7}, {%8,%9}, {%0,%1,%2,%3};"               \
        : "+f"(c[CT][0]), "+f"(c[CT][1]), "+f"(c[CT][2]), "+f"(c[CT][3])      \
        : "r"(AH0), "r"(AH1), "r"(AH2), "r"(AH3), "r"(B0), "r"(B1))
                MMA(nt * 2,     bh0, bh1, ah[0], ah[1], ah[2], ah[3]);
                MMA(nt * 2,     bh0, bh1, al[0], al[1], al[2], al[3]);
                MMA(nt * 2,     bl0, bl1, ah[0], ah[1], ah[2], ah[3]);
                MMA(nt * 2 + 1, bh2, bh3, ah[0], ah[1], ah[2], ah[3]);
                MMA(nt * 2 + 1, bh2, bh3, al[0], al[1], al[2], al[3]);
                MMA(nt * 2 + 1, bl2, bl3, ah[0], ah[1], ah[2], ah[3]);
#undef MMA
            }
        }
        __syncthreads();
    }

    // epilogue: scale by dinv, store fp16 into interleaved Y (node row = 512B)
    float dv0 = (m0 < M2) ? g_dinv[(m0 < NN) ? m0 : m0 - NN] : 0.f;
    float dv1 = (m1 < M2) ? g_dinv[(m1 < NN) ? m1 : m1 - NN] : 0.f;
    size_t y0 = (m0 < NN) ? ((size_t)m0 * 256) : ((size_t)(m0 - NN) * 256 + 128);
    size_t y1 = (m1 < NN) ? ((size_t)m1 * 256) : ((size_t)(m1 - NN) * 256 + 128);
#pragma unroll
    for (int t = 0; t < 16; t++) {
        int col = t * 8 + tig * 2;
        if (m0 < M2)
            *(unsigned*)(g_Yh + y0 + col) =
                h2_bits(__floats2half2_rn(dv0 * c[t][0], dv0 * c[t][1]));
        if (m1 < M2)
            *(unsigned*)(g_Yh + y1 + col) =
                h2_bits(__floats2half2_rn(dv1 * c[t][2], dv1 * c[t][3]));
    }
}

// ------- aggregation: warp/node, 16B/lane/edge, 8-edge unroll ----------------
__device__ __forceinline__ void acc_q(float* a, uint4 p) {
#pragma unroll
    for (int i = 0; i < 4; i++) {
        float2 f = __half22float2(((__half2*)&p)[i]);
        a[2 * i] += f.x; a[2 * i + 1] += f.y;
    }
}

__global__ __launch_bounds__(256) void agg_kernel(const float* __restrict__ bias,
                                                  const float* __restrict__ aptr) {
    int c    = (blockIdx.x * blockDim.x + threadIdx.x) >> 5;
    int lane = threadIdx.x & 31;
    if (c >= NN) return;

    const uint4* Yq = (const uint4*)g_Yh;   // 32 uint4 per node row (512B)
    float a[8] = {0, 0, 0, 0, 0, 0, 0, 0};
    acc_q(a, Yq[(size_t)c * 32 + lane]);    // self loop

    int e = g_rowptr[c], e1 = g_rowptr[c + 1];
    for (; e + 8 <= e1; e += 8) {
        int idx[8];
#pragma unroll
        for (int j = 0; j < 8; j++) idx[j] = g_src[e + j];
        uint4 p[8];
#pragma unroll
        for (int j = 0; j < 8; j++) p[j] = Yq[(size_t)idx[j] * 32 + lane];
#pragma unroll
        for (int j = 0; j < 8; j++) acc_q(a, p[j]);
    }
    if (e + 4 <= e1) {
        int i0 = g_src[e], i1 = g_src[e + 1], i2 = g_src[e + 2], i3 = g_src[e + 3];
        uint4 p0 = Yq[(size_t)i0 * 32 + lane];
        uint4 p1 = Yq[(size_t)i1 * 32 + lane];
        uint4 p2 = Yq[(size_t)i2 * 32 + lane];
        uint4 p3 = Yq[(size_t)i3 * 32 + lane];
        acc_q(a, p0); acc_q(a, p1); acc_q(a, p2); acc_q(a, p3);
        e += 4;
    }
    for (; e < e1; e++)
        acc_q(a, Yq[(size_t)g_src[e] * 32 + lane]);

    float dv = g_dinv[c];
    float alpha = aptr[0];
    int colb = (lane & 15) * 8;
    float4 b0 = *(const float4*)(bias + colb);
    float4 b1 = *(const float4*)(bias + colb + 4);
    float4 o0, o1;
    o0.x = fmaf(dv, a[0], b0.x); o0.x = (o0.x >= 0.f) ? o0.x : alpha * o0.x;
    o0.y = fmaf(dv, a[1], b0.y); o0.y = (o0.y >= 0.f) ? o0.y : alpha * o0.y;
    o0.z = fmaf(dv, a[2], b0.z); o0.z = (o0.z >= 0.f) ? o0.z : alpha * o0.z;
    o0.w = fmaf(dv, a[3], b0.w); o0.w = (o0.w >= 0.f) ? o0.w : alpha * o0.w;
    o1.x = fmaf(dv, a[4], b1.x); o1.x = (o1.x >= 0.f) ? o1.x : alpha * o1.x;
    o1.y = fmaf(dv, a[5], b1.y); o1.y = (o1.y >= 0.f) ? o1.y : alpha * o1.y;
    o1.z = fmaf(dv, a[6], b1.z); o1.z = (o1.z >= 0.f) ? o1.z : alpha * o1.z;
    o1.w = fmaf(dv, a[7], b1.w); o1.w = (o1.w >= 0.f) ? o1.w : alpha * o1.w;

    size_t row = (size_t)(c + (lane >> 4) * NN) * D + colb;
    *(float4*)(g_H + row)     = o0;
    *(float4*)(g_H + row + 4) = o1;
}

// ---------------- readout ----------------
__global__ void colsum_kernel() {
    int col  = threadIdx.x & 127;
    int half = threadIdx.x >> 7;
    float s = 0.f;
    for (int r = blockIdx.x * 2 + half; r < NN; r += gridDim.x * 2)
        s += g_H[(size_t)r * D + col];
    __shared__ float sh[256];
    sh[threadIdx.x] = s;
    __syncthreads();
    if (half == 0) atomicAdd(&g_colsum[col], s + sh[threadIdx.x + 128]);
}

__global__ void wc_kernel(const float* __restrict__ Wb) {
    __shared__ float cs[128];
    int t = threadIdx.x;
    float m = g_colsum[t] / (float)NN;
    cs[t] = 1.f / (1.f + expf(-m));
    __syncthreads();
    float s = 0.f;
#pragma unroll 4
    for (int j = 0; j < 128; j++) s += Wb[(size_t)t * 128 + j] * cs[j];
    g_wc[t] = s;
}

// ---------------- scores ----------------
__global__ __launch_bounds__(256) void score_kernel(float* __restrict__ out,
                                                    const float* __restrict__ bb) {
    __shared__ float wcs[128];
    if (threadIdx.x < 128) wcs[threadIdx.x] = g_wc[threadIdx.x];
    __syncthreads();
    int warp = (blockIdx.x * blockDim.x + threadIdx.x) >> 5;
    int lane = threadIdx.x & 31;
    if (warp >= M2) return;
    const float4* H4 = (const float4*)g_H;
    float4 h = H4[(size_t)warp * 32 + lane];
    float w0 = wcs[lane * 4 + 0], w1 = wcs[lane * 4 + 1];
    float w2 = wcs[lane * 4 + 2], w3 = wcs[lane * 4 + 3];
    float s = h.x * w0 + h.y * w1 + h.z * w2 + h.w * w3;
#pragma unroll
    for (int o = 16; o > 0; o >>= 1) s += __shfl_xor_sync(0xffffffffu, s, o);
    if (lane == 0) out[warp] = s + bb[0];
}

// ---------------- launch ----------------
extern "C" void kernel_launch(void* const* d_in, const int* in_sizes, int n_in,
                              void* d_out, int out_size) {
    const float* seq1 = (const float*)d_in[0];
    const float* seq2 = (const float*)d_in[1];
    const void*  ei   = d_in[2];
    const float* W1   = (const float*)d_in[3];
    const float* b1   = (const float*)d_in[4];
    const float* W2   = (const float*)d_in[5];
    const float* b2   = (const float*)d_in[6];
    const float* W3   = (const float*)d_in[7];
    const float* b3   = (const float*)d_in[8];
    const float* ap   = (const float*)d_in[9];
    const float* Wb   = (const float*)d_in[10];
    const float* bb   = (const float*)d_in[11];

    const int e8_blocks  = (EE / 8 + 255) / 256;
    const int agg_blocks = (NN * 32 + 255) / 256;
    const int sc_blocks  = (M2 * 32 + 255) / 256;

    init_kernel<<<(NN + 255) / 256, 256>>>((const int*)ei);
    hist_kernel<<<e8_blocks, 256>>>(ei);
    scan_kernel<<<1, 1024>>>();
    fill_kernel<<<e8_blocks, 256>>>(ei);

    gemm_mma_kernel<<<GEMM_BLOCKS, 256>>>(W1, seq1, seq2);
    agg_kernel<<<agg_blocks, 256>>>(b1, ap);

    gemm_mma_kernel<<<GEMM_BLOCKS, 256>>>(W2, nullptr, nullptr);
    agg_kernel<<<agg_blocks, 256>>>(b2, ap);

    gemm_mma_kernel<<<GEMM_BLOCKS, 256>>>(W3, nullptr, nullptr);
    agg_kernel<<<agg_blocks, 256>>>(b3, ap);

    colsum_kernel<<<100, 256>>>();
    wc_kernel<<<1, 128>>>(Wb);

    score_kernel<<<sc_blocks, 256>>>((float*)d_out, bb);
}